// round 4
// baseline (speedup 1.0000x reference)
#include <cuda_runtime.h>
#include <cuda_bf16.h>
#include <cstdint>

// Problem constants
#define B_   16
#define N_   256
#define DIN_ 64
#define DOUT_ 64
#define K_   128           // top-k = N * 0.5
#define XPAD 68            // padded row stride (floats) for bank-conflict-free LDS.128

// Scratch (allocation-free: __device__ globals)
__device__ float g_h[B_ * N_ * DOUT_];
__device__ float g_scores[B_ * N_];

// Dynamic smem layout (floats):
//  xs   [256][68]  = 17408
//  wt   [64][64]   =  4096   (W_att transposed: wt[e][d])
//  batt [64], aw [64]
//  sA   [256]
//  red  [256]
//  part [4][64]    = 256
//  aggv [64]
#define SM_XS    0
#define SM_WT    (SM_XS + 256 * XPAD)
#define SM_BATT  (SM_WT + 64 * 64)
#define SM_AW    (SM_BATT + 64)
#define SM_SA    (SM_AW + 64)
#define SM_RED   (SM_SA + 256)
#define SM_PART  (SM_RED + 256)
#define SM_AGG   (SM_PART + 256)
#define SM_TOTAL (SM_AGG + 64)
#define SMEM_BYTES (SM_TOTAL * sizeof(float))

__global__ void __launch_bounds__(256, 2)
attn_kernel(const float* __restrict__ x,
            const float* __restrict__ W_att, const float* __restrict__ b_att,
            const float* __restrict__ att_w,
            const float* __restrict__ W_pwa, const float* __restrict__ b_pwa,
            const float* __restrict__ W_pna, const float* __restrict__ b_pna,
            const float* __restrict__ bn_scale, const float* __restrict__ bn_bias,
            const float* __restrict__ pool_w, const float* __restrict__ pool_b)
{
    extern __shared__ float sm[];
    float* xs   = sm + SM_XS;
    float* wt   = sm + SM_WT;
    float* batt = sm + SM_BATT;
    float* aw   = sm + SM_AW;
    float* sA   = sm + SM_SA;
    float* red  = sm + SM_RED;
    float* part = sm + SM_PART;
    float* aggv = sm + SM_AGG;

    const int b   = blockIdx.y;
    const int i   = blockIdx.x;
    const int tid = threadIdx.x;

    // ---- cooperative loads ----
    // x_b: 256x64 floats -> padded smem rows (float4 granularity)
    {
        const float4* xb = (const float4*)(x + (size_t)b * N_ * DIN_);
        #pragma unroll
        for (int t = tid; t < 256 * 16; t += 256) {
            int r = t >> 4, c = t & 15;
            ((float4*)(xs + r * XPAD))[c] = xb[t];
        }
    }
    // W_att transpose: wt[e*64+d] = W_att[d*64+e]
    #pragma unroll
    for (int t = tid; t < 4096; t += 256) {
        int d = t >> 6, e = t & 63;
        wt[e * 64 + d] = W_att[t];
    }
    if (tid < 64) { batt[tid] = b_att[tid]; aw[tid] = att_w[tid]; }
    __syncthreads();

    // ---- per-thread: j = tid, compute logit[b,i,j] ----
    const float* xi = xs + i   * XPAD;
    const float* xj = xs + tid * XPAD;

    float p[64];
    #pragma unroll
    for (int d4 = 0; d4 < 16; d4++) {
        float4 a  = ((const float4*)xi)[d4];
        float4 bb = ((const float4*)xj)[d4];
        p[4 * d4 + 0] = a.x * bb.x;
        p[4 * d4 + 1] = a.y * bb.y;
        p[4 * d4 + 2] = a.z * bb.z;
        p[4 * d4 + 3] = a.w * bb.w;
    }

    float lg = 0.0f;
    #pragma unroll 2
    for (int e = 0; e < 64; e++) {
        const float4* wr = (const float4*)(wt + e * 64);
        float a0 = batt[e], a1 = 0.f, a2 = 0.f, a3 = 0.f;
        #pragma unroll
        for (int d4 = 0; d4 < 16; d4 += 4) {
            float4 w0 = wr[d4 + 0];
            a0 = fmaf(p[4*d4 + 0],  w0.x, a0); a0 = fmaf(p[4*d4 + 1],  w0.y, a0);
            a0 = fmaf(p[4*d4 + 2],  w0.z, a0); a0 = fmaf(p[4*d4 + 3],  w0.w, a0);
            float4 w1 = wr[d4 + 1];
            a1 = fmaf(p[4*d4 + 4],  w1.x, a1); a1 = fmaf(p[4*d4 + 5],  w1.y, a1);
            a1 = fmaf(p[4*d4 + 6],  w1.z, a1); a1 = fmaf(p[4*d4 + 7],  w1.w, a1);
            float4 w2 = wr[d4 + 2];
            a2 = fmaf(p[4*d4 + 8],  w2.x, a2); a2 = fmaf(p[4*d4 + 9],  w2.y, a2);
            a2 = fmaf(p[4*d4 +10],  w2.z, a2); a2 = fmaf(p[4*d4 +11],  w2.w, a2);
            float4 w3 = wr[d4 + 3];
            a3 = fmaf(p[4*d4 +12],  w3.x, a3); a3 = fmaf(p[4*d4 +13],  w3.y, a3);
            a3 = fmaf(p[4*d4 +14],  w3.z, a3); a3 = fmaf(p[4*d4 +15],  w3.w, a3);
        }
        float v = (a0 + a1) + (a2 + a3);
        lg = fmaf(tanhf(v), aw[e], lg);
    }
    lg *= 0.5f;   // / TEMP

    // ---- softmax over j (block of 256 = one row) ----
    red[tid] = lg; __syncthreads();
    #pragma unroll
    for (int s = 128; s > 0; s >>= 1) {
        if (tid < s) red[tid] = fmaxf(red[tid], red[tid + s]);
        __syncthreads();
    }
    float mx = red[0]; __syncthreads();

    float w = __expf(lg - mx);   // normalized ratio -> approx error cancels
    red[tid] = w; __syncthreads();
    #pragma unroll
    for (int s = 128; s > 0; s >>= 1) {
        if (tid < s) red[tid] += red[tid + s];
        __syncthreads();
    }
    float inv_sum = 1.0f / red[0]; __syncthreads();
    sA[tid] = w * inv_sum;
    __syncthreads();

    // ---- agg[d] = sum_j A[j] * x[b,j,d] ----
    {
        int d = tid & 63, g = tid >> 6;
        float s = 0.f;
        int j0 = g * 64;
        #pragma unroll 8
        for (int j = j0; j < j0 + 64; j++)
            s = fmaf(sA[j], xs[j * XPAD + d], s);
        part[g * 64 + d] = s;
    }
    __syncthreads();
    if (tid < 64)
        aggv[tid] = (part[tid] + part[64 + tid]) + (part[128 + tid] + part[192 + tid]);
    __syncthreads();

    // ---- h = agg@W_pwa + b_pwa + x_i@W_pna + b_pna, BN, SELU, score ----
    if (tid < 64) {
        const int e = tid;
        float h = b_pwa[e] + b_pna[e];
        #pragma unroll 8
        for (int d = 0; d < 64; d++) {
            h = fmaf(aggv[d], W_pwa[d * 64 + e], h);
            h = fmaf(xi[d],   W_pna[d * 64 + e], h);
        }
        // BatchNorm eval (mean 0, var 1)
        h = fmaf(h, bn_scale[e] * rsqrtf(1.0f + 1e-5f), bn_bias[e]);
        // SELU
        const float SC = 1.0507009873554805f;
        const float AL = 1.6732632423543772f;
        h = (h > 0.f) ? SC * h : SC * AL * expm1f(h);
        g_h[((size_t)b * N_ + i) * DOUT_ + e] = h;
        red[e] = h * pool_w[e];
    }
    __syncthreads();
    if (tid == 0) {
        float s = 0.f;
        #pragma unroll
        for (int e = 0; e < 64; e++) s += red[e];
        s += pool_b[0];
        g_scores[b * N_ + i] = 1.0f / (1.0f + expf(-s));
    }
}

// Per-batch exact top-k (sorted desc by score, asc index tiebreak like lax.top_k)
__global__ void topk_gather_kernel(float* __restrict__ out)
{
    __shared__ unsigned long long keys[N_];
    const int b = blockIdx.x, tid = threadIdx.x;

    float sc = g_scores[b * N_ + tid];
    // sigmoid > 0 -> positive float bits are order-preserving
    keys[tid] = ((unsigned long long)__float_as_uint(sc) << 32)
              | (unsigned)(0xFFFFFFFFu - (unsigned)tid);
    __syncthreads();

    // bitonic sort, final order descending
    for (unsigned k = 2; k <= N_; k <<= 1) {
        for (unsigned j = k >> 1; j > 0; j >>= 1) {
            unsigned ixj = tid ^ j;
            if (ixj > (unsigned)tid) {
                bool desc = ((tid & k) == 0);
                unsigned long long a = keys[tid], c = keys[ixj];
                bool sw = desc ? (a < c) : (a > c);
                if (sw) { keys[tid] = c; keys[ixj] = a; }
            }
            __syncthreads();
        }
    }

    // gather: out[b, r, e] = h[b, idx[r], e] * score[idx[r]]
    for (int t = tid; t < K_ * DOUT_; t += N_) {
        int r = t >> 6, e = t & 63;
        unsigned long long k = keys[r];
        int idx = (int)(0xFFFFFFFFu - (unsigned)(k & 0xFFFFFFFFu));
        float s = __uint_as_float((unsigned)(k >> 32));
        out[((size_t)b * K_ + r) * DOUT_ + e] =
            g_h[((size_t)b * N_ + idx) * DOUT_ + e] * s;
    }
}

extern "C" void kernel_launch(void* const* d_in, const int* in_sizes, int n_in,
                              void* d_out, int out_size)
{
    const float* x        = (const float*)d_in[0];
    const float* W_att    = (const float*)d_in[1];
    const float* b_att    = (const float*)d_in[2];
    const float* att_w    = (const float*)d_in[3];
    const float* W_pwa    = (const float*)d_in[4];
    const float* b_pwa    = (const float*)d_in[5];
    const float* W_pna    = (const float*)d_in[6];
    const float* b_pna    = (const float*)d_in[7];
    const float* bn_scale = (const float*)d_in[8];
    const float* bn_bias  = (const float*)d_in[9];
    const float* pool_w   = (const float*)d_in[10];
    const float* pool_b   = (const float*)d_in[11];
    float* out = (float*)d_out;

    cudaFuncSetAttribute(attn_kernel,
                         cudaFuncAttributeMaxDynamicSharedMemorySize, SMEM_BYTES);

    dim3 grid(N_, B_);
    attn_kernel<<<grid, 256, SMEM_BYTES>>>(x, W_att, b_att, att_w,
                                           W_pwa, b_pwa, W_pna, b_pna,
                                           bn_scale, bn_bias, pool_w, pool_b);
    topk_gather_kernel<<<B_, N_>>>(out);
}

// round 7
// speedup vs baseline: 1.4667x; 1.4667x over previous
#include <cuda_runtime.h>
#include <cuda_bf16.h>
#include <cstdint>

#define B_    16
#define N_    256
#define DIN_  64
#define DOUT_ 64
#define K_    128
#define XPAD  68     // padded row stride (floats)

// Scratch (allocation-free: __device__ globals)
__device__ float g_logits[B_ * N_ * N_];   // 4 MB, L2-resident
__device__ float g_h[B_ * N_ * DOUT_];
__device__ float g_scores[B_ * N_];

// pair index -> (ti, tj) LUT for 8x8 upper triangle (36 pairs)
__constant__ unsigned char c_ti[36] = {
    0,0,0,0,0,0,0,0,
    1,1,1,1,1,1,1,
    2,2,2,2,2,2,
    3,3,3,3,3,
    4,4,4,4,
    5,5,5,
    6,6,
    7};
__constant__ unsigned char c_tj[36] = {
    0,1,2,3,4,5,6,7,
    1,2,3,4,5,6,7,
    2,3,4,5,6,7,
    3,4,5,6,7,
    4,5,6,7,
    5,6,7,
    6,7,
    7};

// fast tanh: 2 MUFU + few ALU, rel err ~1e-6, off the fma pipe
__device__ __forceinline__ float tanh_fast(float v) {
    float av = fabsf(v);
    float t  = __expf(-2.0f * av);
    float r  = __fdividef(1.0f - t, 1.0f + t);
    return copysignf(r, v);
}

// ============================================================================
// Kernel 1: symmetric logits. Grid (36 tile-pairs, B). Block 256.
// Tile pair (ti<=tj): compute 32x32 logit tile (i in ti-tile, j in tj-tile),
// write it coalesced, mirror via smem transpose when ti!=tj.
// Thread map: warp w -> i_local = w + 8q (q=0..3), lane = j_local.
// ============================================================================
__global__ void __launch_bounds__(256, 2)
logits_kernel(const float* __restrict__ x,
              const float* __restrict__ W_att, const float* __restrict__ b_att,
              const float* __restrict__ att_w)
{
    __shared__ float xi_s[32 * XPAD];
    __shared__ float xj_s[32 * XPAD];
    __shared__ float wt[64 * 64];        // W_att transposed: wt[e][d]
    __shared__ float batt[64], aw[64];
    __shared__ float st[32 * 33];        // staging for mirror transpose

    const int b   = blockIdx.y;
    const int tid = threadIdx.x;

    const int ti  = c_ti[blockIdx.x];
    const int tj  = c_tj[blockIdx.x];
    const int gi0 = ti * 32, gj0 = tj * 32;

    // cooperative loads
    {
        const float4* xa = (const float4*)(x + ((size_t)b * N_ + gi0) * DIN_);
        const float4* xb = (const float4*)(x + ((size_t)b * N_ + gj0) * DIN_);
        #pragma unroll
        for (int t = tid; t < 512; t += 256) {
            int r = t >> 4, c = t & 15;
            ((float4*)(xi_s + r * XPAD))[c] = xa[t];
            ((float4*)(xj_s + r * XPAD))[c] = xb[t];
        }
    }
    #pragma unroll
    for (int t = tid; t < 4096; t += 256) {
        int d = t >> 6, e = t & 63;
        wt[e * 64 + d] = W_att[t];
    }
    if (tid < 64) { batt[tid] = b_att[tid]; aw[tid] = att_w[tid]; }
    __syncthreads();

    const int jl = tid & 31;
    const int w  = tid >> 5;
    const float* xj = xj_s + jl * XPAD;

    #pragma unroll
    for (int q = 0; q < 4; q++) {
        const int il = w + 8 * q;
        const float* xi = xi_s + il * XPAD;

        float pr[64];
        #pragma unroll
        for (int c = 0; c < 16; c++) {
            float4 a  = ((const float4*)xi)[c];   // warp-broadcast LDS
            float4 bb = ((const float4*)xj)[c];   // per-lane row
            pr[4*c + 0] = a.x * bb.x;
            pr[4*c + 1] = a.y * bb.y;
            pr[4*c + 2] = a.z * bb.z;
            pr[4*c + 3] = a.w * bb.w;
        }

        float lg = 0.0f;
        #pragma unroll 2
        for (int e = 0; e < 64; e++) {
            const float4* wr = (const float4*)(wt + e * 64);  // warp-broadcast
            float a0 = batt[e], a1 = 0.f, a2 = 0.f, a3 = 0.f;
            #pragma unroll
            for (int c = 0; c < 16; c += 4) {
                float4 w0 = wr[c + 0];
                a0 = fmaf(pr[4*c + 0],  w0.x, a0); a0 = fmaf(pr[4*c + 1],  w0.y, a0);
                a0 = fmaf(pr[4*c + 2],  w0.z, a0); a0 = fmaf(pr[4*c + 3],  w0.w, a0);
                float4 w1 = wr[c + 1];
                a1 = fmaf(pr[4*c + 4],  w1.x, a1); a1 = fmaf(pr[4*c + 5],  w1.y, a1);
                a1 = fmaf(pr[4*c + 6],  w1.z, a1); a1 = fmaf(pr[4*c + 7],  w1.w, a1);
                float4 w2 = wr[c + 2];
                a2 = fmaf(pr[4*c + 8],  w2.x, a2); a2 = fmaf(pr[4*c + 9],  w2.y, a2);
                a2 = fmaf(pr[4*c +10],  w2.z, a2); a2 = fmaf(pr[4*c +11],  w2.w, a2);
                float4 w3 = wr[c + 3];
                a3 = fmaf(pr[4*c +12],  w3.x, a3); a3 = fmaf(pr[4*c +13],  w3.y, a3);
                a3 = fmaf(pr[4*c +14],  w3.z, a3); a3 = fmaf(pr[4*c +15],  w3.w, a3);
            }
            float v = (a0 + a1) + (a2 + a3);
            lg = fmaf(tanh_fast(v), aw[e], lg);
        }
        lg *= 0.5f;   // / TEMP

        g_logits[((size_t)b * N_ + gi0 + il) * N_ + gj0 + jl] = lg;  // coalesced
        st[il * 33 + jl] = lg;
    }

    if (ti != tj) {
        __syncthreads();
        // mirror: logits[b, gj0+r, gi0+c] = st[c][r]; coalesced writes
        #pragma unroll
        for (int t = tid; t < 1024; t += 256) {
            int r = t >> 5, c = t & 31;
            g_logits[((size_t)b * N_ + gj0 + r) * N_ + gi0 + c] = st[c * 33 + r];
        }
    }
}

// ============================================================================
// Kernel 2: per-(b,i) row softmax + aggregation + h + BN + SELU + score
// ============================================================================
__global__ void __launch_bounds__(256)
epilogue_kernel(const float* __restrict__ x,
                const float* __restrict__ W_pwa, const float* __restrict__ b_pwa,
                const float* __restrict__ W_pna, const float* __restrict__ b_pna,
                const float* __restrict__ bn_scale, const float* __restrict__ bn_bias,
                const float* __restrict__ pool_w, const float* __restrict__ pool_b)
{
    __shared__ float red[256];
    __shared__ float sA[256];
    __shared__ float part[256];
    __shared__ float aggv[64];
    __shared__ float xi_sh[64];

    const int b = blockIdx.y, i = blockIdx.x, tid = threadIdx.x;

    float lg = g_logits[((size_t)b * N_ + i) * N_ + tid];

    // max reduce
    red[tid] = lg; __syncthreads();
    #pragma unroll
    for (int s = 128; s > 0; s >>= 1) {
        if (tid < s) red[tid] = fmaxf(red[tid], red[tid + s]);
        __syncthreads();
    }
    float mx = red[0]; __syncthreads();

    float wexp = __expf(lg - mx);
    red[tid] = wexp; __syncthreads();
    #pragma unroll
    for (int s = 128; s > 0; s >>= 1) {
        if (tid < s) red[tid] += red[tid + s];
        __syncthreads();
    }
    float inv_sum = 1.0f / red[0]; __syncthreads();
    sA[tid] = wexp * inv_sum;
    if (tid < 64) xi_sh[tid] = x[((size_t)b * N_ + i) * DIN_ + tid];
    __syncthreads();

    // agg[d] = sum_j A[j] x[b,j,d]  (4 j-quarters in parallel)
    {
        const int d = tid & 63, g = tid >> 6;
        const float* xb = x + (size_t)b * N_ * DIN_;
        float s = 0.f;
        const int j0 = g * 64;
        #pragma unroll 8
        for (int j = j0; j < j0 + 64; j++)
            s = fmaf(sA[j], xb[j * DIN_ + d], s);
        part[tid] = s;
    }
    __syncthreads();
    if (tid < 64)
        aggv[tid] = (part[tid] + part[64 + tid]) + (part[128 + tid] + part[192 + tid]);
    __syncthreads();

    if (tid < 64) {
        const int e = tid;
        float h = b_pwa[e] + b_pna[e];
        #pragma unroll 8
        for (int d = 0; d < 64; d++) {
            h = fmaf(aggv[d],  W_pwa[d * 64 + e], h);
            h = fmaf(xi_sh[d], W_pna[d * 64 + e], h);
        }
        h = fmaf(h, bn_scale[e] * rsqrtf(1.0f + 1e-5f), bn_bias[e]);
        const float SC = 1.0507009873554805f;
        const float AL = 1.6732632423543772f;
        h = (h > 0.f) ? SC * h : SC * AL * expm1f(h);
        g_h[((size_t)b * N_ + i) * DOUT_ + e] = h;
        red[e] = h * pool_w[e];
    }
    __syncthreads();
    if (tid < 32) {
        float v = red[tid] + red[tid + 32];
        #pragma unroll
        for (int o = 16; o > 0; o >>= 1) v += __shfl_down_sync(0xffffffffu, v, o);
        if (tid == 0) {
            v += pool_b[0];
            g_scores[b * N_ + i] = 1.0f / (1.0f + __expf(-v));
        }
    }
}

// ============================================================================
// Kernel 3: sync-free exact top-k by rank counting + coalesced gather
// (key = score bits desc, index asc tiebreak -> matches lax.top_k ordering)
// ============================================================================
__global__ void __launch_bounds__(256)
topk_kernel(float* __restrict__ out)
{
    __shared__ unsigned long long keys[N_];
    __shared__ int   inv[K_];
    __shared__ float ssc[K_];
    const int b = blockIdx.x, tid = threadIdx.x;

    float sc = g_scores[b * N_ + tid];
    unsigned long long mykey =
        ((unsigned long long)__float_as_uint(sc) << 32)
        | (unsigned)(0xFFFFFFFFu - (unsigned)tid);
    keys[tid] = mykey;
    __syncthreads();

    int rank = 0;
    #pragma unroll 8
    for (int j = 0; j < N_; j++) rank += (keys[j] > mykey);   // broadcast LDS
    if (rank < K_) { inv[rank] = tid; ssc[rank] = sc; }
    __syncthreads();

    #pragma unroll
    for (int t = tid; t < K_ * DOUT_; t += N_) {
        int r = t >> 6, e = t & 63;
        out[((size_t)b * K_ + r) * DOUT_ + e] =
            g_h[((size_t)b * N_ + inv[r]) * DOUT_ + e] * ssc[r];
    }
}

extern "C" void kernel_launch(void* const* d_in, const int* in_sizes, int n_in,
                              void* d_out, int out_size)
{
    const float* x        = (const float*)d_in[0];
    const float* W_att    = (const float*)d_in[1];
    const float* b_att    = (const float*)d_in[2];
    const float* att_w    = (const float*)d_in[3];
    const float* W_pwa    = (const float*)d_in[4];
    const float* b_pwa    = (const float*)d_in[5];
    const float* W_pna    = (const float*)d_in[6];
    const float* b_pna    = (const float*)d_in[7];
    const float* bn_scale = (const float*)d_in[8];
    const float* bn_bias  = (const float*)d_in[9];
    const float* pool_w   = (const float*)d_in[10];
    const float* pool_b   = (const float*)d_in[11];
    float* out = (float*)d_out;

    logits_kernel<<<dim3(36, B_), 256>>>(x, W_att, b_att, att_w);
    epilogue_kernel<<<dim3(N_, B_), 256>>>(x, W_pwa, b_pwa, W_pna, b_pna,
                                           bn_scale, bn_bias, pool_w, pool_b);
    topk_kernel<<<B_, 256>>>(out);
}

// round 10
// speedup vs baseline: 1.8714x; 1.2759x over previous
#include <cuda_runtime.h>
#include <cuda_bf16.h>
#include <cstdint>

#define B_    16
#define N_    256
#define DIN_  64
#define DOUT_ 64
#define K_    128
#define XPAD  68     // padded row stride (floats)

typedef unsigned long long u64t;

// Scratch (allocation-free: __device__ globals)
__device__ float g_logits[B_ * N_ * N_];   // 4 MB, L2-resident
__device__ float g_h[B_ * N_ * DOUT_];
__device__ float g_scores[B_ * N_];

// pair index -> (ti, tj) LUT for 8x8 upper triangle (36 pairs)
__constant__ unsigned char c_ti[36] = {
    0,0,0,0,0,0,0,0, 1,1,1,1,1,1,1, 2,2,2,2,2,2,
    3,3,3,3,3, 4,4,4,4, 5,5,5, 6,6, 7};
__constant__ unsigned char c_tj[36] = {
    0,1,2,3,4,5,6,7, 1,2,3,4,5,6,7, 2,3,4,5,6,7,
    3,4,5,6,7, 4,5,6,7, 5,6,7, 6,7, 7};

// packed fp32x2 ops (Blackwell; ptxas never auto-fuses these)
__device__ __forceinline__ u64t ffma2(u64t a, u64t b, u64t c) {
    u64t d;
    asm("fma.rn.f32x2 %0, %1, %2, %3;" : "=l"(d) : "l"(a), "l"(b), "l"(c));
    return d;
}
__device__ __forceinline__ u64t fmul2(u64t a, u64t b) {
    u64t d;
    asm("mul.rn.f32x2 %0, %1, %2;" : "=l"(d) : "l"(a), "l"(b));
    return d;
}
__device__ __forceinline__ u64t fadd2(u64t a, u64t b) {
    u64t d;
    asm("add.rn.f32x2 %0, %1, %2;" : "=l"(d) : "l"(a), "l"(b));
    return d;
}

// fast tanh: 2 MUFU + few ALU, rel err ~1e-6, off the fma pipe
__device__ __forceinline__ float tanh_fast(float v) {
    float av = fabsf(v);
    float t  = __expf(-2.0f * av);
    float r  = __fdividef(1.0f - t, 1.0f + t);
    return copysignf(r, v);
}

// ============================================================================
// Kernel 1: symmetric logits via packed f32x2 FMA.
// Grid (36 tile-pairs, B). Block 256. Thread: lane=j_local, warp+8q=i_local.
// ============================================================================
__global__ void __launch_bounds__(256, 2)
logits_kernel(const float* __restrict__ x,
              const float* __restrict__ W_att, const float* __restrict__ b_att,
              const float* __restrict__ att_w)
{
    __shared__ __align__(16) float xi_s[32 * XPAD];
    __shared__ __align__(16) float xj_s[32 * XPAD];
    __shared__ __align__(16) float wt[64 * 64];   // W_att transposed: wt[e][d]
    __shared__ float batt[64], aw[64];
    __shared__ float st[32 * 33];                 // mirror transpose staging

    const int b   = blockIdx.y;
    const int tid = threadIdx.x;

    const int ti  = c_ti[blockIdx.x];
    const int tj  = c_tj[blockIdx.x];
    const int gi0 = ti * 32, gj0 = tj * 32;

    {
        const float4* xa = (const float4*)(x + ((size_t)b * N_ + gi0) * DIN_);
        const float4* xb = (const float4*)(x + ((size_t)b * N_ + gj0) * DIN_);
        #pragma unroll
        for (int t = tid; t < 512; t += 256) {
            int r = t >> 4, c = t & 15;
            ((float4*)(xi_s + r * XPAD))[c] = xa[t];
            ((float4*)(xj_s + r * XPAD))[c] = xb[t];
        }
    }
    #pragma unroll
    for (int t = tid; t < 4096; t += 256) {
        int d = t >> 6, e = t & 63;
        wt[e * 64 + d] = W_att[t];
    }
    if (tid < 64) { batt[tid] = b_att[tid]; aw[tid] = att_w[tid]; }
    __syncthreads();

    const int jl = tid & 31;
    const int w  = tid >> 5;
    const float* xj = xj_s + jl * XPAD;

    #pragma unroll
    for (int q = 0; q < 4; q++) {
        const int il = w + 8 * q;
        const float* xi = xi_s + il * XPAD;

        // pr packed: 32 f32x2 = 64 floats
        u64t pr2[32];
        #pragma unroll
        for (int c = 0; c < 16; c++) {
            ulonglong2 a  = ((const ulonglong2*)xi)[c];   // warp-broadcast LDS
            ulonglong2 bb = ((const ulonglong2*)xj)[c];   // per-lane row
            pr2[2*c + 0] = fmul2(a.x, bb.x);
            pr2[2*c + 1] = fmul2(a.y, bb.y);
        }

        float lg = 0.0f;
        #pragma unroll 4
        for (int e = 0; e < 64; e++) {
            const ulonglong2* wr = (const ulonglong2*)(wt + e * 64); // broadcast
            u64t a0 = 0ull, a1 = 0ull, a2 = 0ull, a3 = 0ull;
            #pragma unroll
            for (int c = 0; c < 4; c++) {
                ulonglong2 w0 = wr[c];
                a0 = ffma2(pr2[2*c + 0],  w0.x, a0);
                a0 = ffma2(pr2[2*c + 1],  w0.y, a0);
                ulonglong2 w1 = wr[c + 4];
                a1 = ffma2(pr2[2*c + 8],  w1.x, a1);
                a1 = ffma2(pr2[2*c + 9],  w1.y, a1);
                ulonglong2 w2 = wr[c + 8];
                a2 = ffma2(pr2[2*c + 16], w2.x, a2);
                a2 = ffma2(pr2[2*c + 17], w2.y, a2);
                ulonglong2 w3 = wr[c + 12];
                a3 = ffma2(pr2[2*c + 24], w3.x, a3);
                a3 = ffma2(pr2[2*c + 25], w3.y, a3);
            }
            u64t s = fadd2(fadd2(a0, a1), fadd2(a2, a3));
            float lo = __uint_as_float((unsigned)(s & 0xFFFFFFFFull));
            float hi = __uint_as_float((unsigned)(s >> 32));
            float v  = (lo + hi) + batt[e];
            lg = fmaf(tanh_fast(v), aw[e], lg);
        }
        lg *= 0.5f;   // / TEMP

        g_logits[((size_t)b * N_ + gi0 + il) * N_ + gj0 + jl] = lg;  // coalesced
        st[il * 33 + jl] = lg;
    }

    if (ti != tj) {
        __syncthreads();
        #pragma unroll
        for (int t = tid; t < 1024; t += 256) {
            int r = t >> 5, c = t & 31;
            g_logits[((size_t)b * N_ + gj0 + r) * N_ + gi0 + c] = st[c * 33 + r];
        }
    }
}

// ============================================================================
// Kernel 2: warp-per-row epilogue. Grid (32, B), block 256 = 8 warps.
// No __syncthreads; shfl reductions only.
// ============================================================================
__global__ void __launch_bounds__(256)
epilogue_kernel(const float* __restrict__ x,
                const float* __restrict__ W_pwa, const float* __restrict__ b_pwa,
                const float* __restrict__ W_pna, const float* __restrict__ b_pna,
                const float* __restrict__ bn_scale, const float* __restrict__ bn_bias,
                const float* __restrict__ pool_w, const float* __restrict__ pool_b)
{
    __shared__ float A_sm[8][256];
    __shared__ float agg_sm[8][64];

    const int b    = blockIdx.y;
    const int warp = threadIdx.x >> 5;
    const int lane = threadIdx.x & 31;
    const int i    = blockIdx.x * 8 + warp;

    // softmax over row i (8 logits per lane, stride 32: coalesced)
    const float* lrow = g_logits + ((size_t)b * N_ + i) * N_;
    float lg[8];
    #pragma unroll
    for (int k = 0; k < 8; k++) lg[k] = lrow[lane + 32 * k];
    float mx = lg[0];
    #pragma unroll
    for (int k = 1; k < 8; k++) mx = fmaxf(mx, lg[k]);
    #pragma unroll
    for (int o = 16; o; o >>= 1) mx = fmaxf(mx, __shfl_xor_sync(~0u, mx, o));
    float wv[8], sum = 0.f;
    #pragma unroll
    for (int k = 0; k < 8; k++) { wv[k] = __expf(lg[k] - mx); sum += wv[k]; }
    #pragma unroll
    for (int o = 16; o; o >>= 1) sum += __shfl_xor_sync(~0u, sum, o);
    float inv = 1.0f / sum;
    #pragma unroll
    for (int k = 0; k < 8; k++) A_sm[warp][lane + 32 * k] = wv[k] * inv;
    __syncwarp();

    // agg[d] for d = 2*lane, 2*lane+1
    const float* xb = x + (size_t)b * N_ * DIN_;
    const float* asrc = A_sm[warp];
    float s0 = 0.f, s1 = 0.f;
    #pragma unroll 4
    for (int j = 0; j < N_; j++) {
        float2 xv = *(const float2*)(xb + j * DIN_ + 2 * lane);
        float aj = asrc[j];
        s0 = fmaf(aj, xv.x, s0);
        s1 = fmaf(aj, xv.y, s1);
    }
    agg_sm[warp][2 * lane]     = s0;
    agg_sm[warp][2 * lane + 1] = s1;
    __syncwarp();

    // h for e = 2*lane, 2*lane+1
    const int e0 = 2 * lane;
    float2 bpw = *(const float2*)(b_pwa + e0);
    float2 bpn = *(const float2*)(b_pna + e0);
    float h0 = bpw.x + bpn.x, h1 = bpw.y + bpn.y;
    const float* aggp = agg_sm[warp];
    const float* xi = xb + i * DIN_;
    #pragma unroll 4
    for (int d = 0; d < DIN_; d++) {
        float2 wp = *(const float2*)(W_pwa + d * 64 + e0);
        float2 wn = *(const float2*)(W_pna + d * 64 + e0);
        float ad = aggp[d];
        float xd = xi[d];
        h0 = fmaf(ad, wp.x, h0); h1 = fmaf(ad, wp.y, h1);
        h0 = fmaf(xd, wn.x, h0); h1 = fmaf(xd, wn.y, h1);
    }
    float2 bs = *(const float2*)(bn_scale + e0);
    float2 bz = *(const float2*)(bn_bias + e0);
    const float inv_std = rsqrtf(1.0f + 1e-5f);
    h0 = fmaf(h0, bs.x * inv_std, bz.x);
    h1 = fmaf(h1, bs.y * inv_std, bz.y);
    const float SC = 1.0507009873554805f;
    const float AL = 1.6732632423543772f;
    h0 = (h0 > 0.f) ? SC * h0 : SC * AL * expm1f(h0);
    h1 = (h1 > 0.f) ? SC * h1 : SC * AL * expm1f(h1);
    *(float2*)(g_h + ((size_t)b * N_ + i) * DOUT_ + e0) = make_float2(h0, h1);

    float2 pw = *(const float2*)(pool_w + e0);
    float v = h0 * pw.x + h1 * pw.y;
    #pragma unroll
    for (int o = 16; o; o >>= 1) v += __shfl_xor_sync(~0u, v, o);
    if (lane == 0)
        g_scores[b * N_ + i] = 1.0f / (1.0f + __expf(-(v + pool_b[0])));
}

// ============================================================================
// Kernel 3: sync-free exact top-k by rank counting + coalesced gather
// ============================================================================
__global__ void __launch_bounds__(256)
topk_kernel(float* __restrict__ out)
{
    __shared__ unsigned long long keys[N_];
    __shared__ int   inv[K_];
    __shared__ float ssc[K_];
    const int b = blockIdx.x, tid = threadIdx.x;

    float sc = g_scores[b * N_ + tid];
    unsigned long long mykey =
        ((unsigned long long)__float_as_uint(sc) << 32)
        | (unsigned)(0xFFFFFFFFu - (unsigned)tid);
    keys[tid] = mykey;
    __syncthreads();

    int rank = 0;
    #pragma unroll 8
    for (int j = 0; j < N_; j++) rank += (keys[j] > mykey);   // broadcast LDS
    if (rank < K_) { inv[rank] = tid; ssc[rank] = sc; }
    __syncthreads();

    #pragma unroll
    for (int t = tid; t < K_ * DOUT_; t += N_) {
        int r = t >> 6, e = t & 63;
        out[((size_t)b * K_ + r) * DOUT_ + e] =
            g_h[((size_t)b * N_ + inv[r]) * DOUT_ + e] * ssc[r];
    }
}

extern "C" void kernel_launch(void* const* d_in, const int* in_sizes, int n_in,
                              void* d_out, int out_size)
{
    const float* x        = (const float*)d_in[0];
    const float* W_att    = (const float*)d_in[1];
    const float* b_att    = (const float*)d_in[2];
    const float* att_w    = (const float*)d_in[3];
    const float* W_pwa    = (const float*)d_in[4];
    const float* b_pwa    = (const float*)d_in[5];
    const float* W_pna    = (const float*)d_in[6];
    const float* b_pna    = (const float*)d_in[7];
    const float* bn_scale = (const float*)d_in[8];
    const float* bn_bias  = (const float*)d_in[9];
    const float* pool_w   = (const float*)d_in[10];
    const float* pool_b   = (const float*)d_in[11];
    float* out = (float*)d_out;

    logits_kernel<<<dim3(36, B_), 256>>>(x, W_att, b_att, att_w);
    epilogue_kernel<<<dim3(32, B_), 256>>>(x, W_pwa, b_pwa, W_pna, b_pna,
                                           bn_scale, bn_bias, pool_w, pool_b);
    topk_kernel<<<B_, 256>>>(out);
}

// round 11
// speedup vs baseline: 2.2911x; 1.2243x over previous
#include <cuda_runtime.h>
#include <cuda_bf16.h>
#include <cstdint>

#define B_    16
#define N_    256
#define DIN_  64
#define DOUT_ 64
#define K_    128
#define XPAD  68     // padded row stride (floats); 68*4 = 272 B = 16B-aligned

typedef unsigned long long u64t;

// Scratch (allocation-free: __device__ globals)
__device__ float g_logits[B_ * N_ * N_];   // 4 MB, L2-resident
__device__ float g_h[B_ * N_ * DOUT_];
__device__ float g_scores[B_ * N_];

// pair index -> (ti, tj) LUT for 8x8 upper triangle (36 pairs)
__constant__ unsigned char c_ti[36] = {
    0,0,0,0,0,0,0,0, 1,1,1,1,1,1,1, 2,2,2,2,2,2,
    3,3,3,3,3, 4,4,4,4, 5,5,5, 6,6, 7};
__constant__ unsigned char c_tj[36] = {
    0,1,2,3,4,5,6,7, 1,2,3,4,5,6,7, 2,3,4,5,6,7,
    3,4,5,6,7, 4,5,6,7, 5,6,7, 6,7, 7};

// packed fp32x2 ops (Blackwell; ptxas never auto-fuses these)
__device__ __forceinline__ u64t ffma2(u64t a, u64t b, u64t c) {
    u64t d;
    asm("fma.rn.f32x2 %0, %1, %2, %3;" : "=l"(d) : "l"(a), "l"(b), "l"(c));
    return d;
}
__device__ __forceinline__ u64t fmul2(u64t a, u64t b) {
    u64t d;
    asm("mul.rn.f32x2 %0, %1, %2;" : "=l"(d) : "l"(a), "l"(b));
    return d;
}
__device__ __forceinline__ u64t fadd2(u64t a, u64t b) {
    u64t d;
    asm("add.rn.f32x2 %0, %1, %2;" : "=l"(d) : "l"(a), "l"(b));
    return d;
}

// fast tanh: 2 MUFU + few ALU, rel err ~1e-6, off the fma pipe
__device__ __forceinline__ float tanh_fast(float v) {
    float av = fabsf(v);
    float t  = __expf(-2.0f * av);
    float r  = __fdividef(1.0f - t, 1.0f + t);
    return copysignf(r, v);
}

// ============================================================================
// Kernel 1: symmetric logits, packed f32x2 FMA, 2 i-rows per e-pass so each
// wt LDS.128 serves two rows. Grid (36 tile-pairs, B). Block 256, 1 CTA/SM.
// ============================================================================
__global__ void __launch_bounds__(256, 1)
logits_kernel(const float* __restrict__ x,
              const float* __restrict__ W_att, const float* __restrict__ b_att,
              const float* __restrict__ att_w)
{
    __shared__ __align__(16) float xi_s[32 * XPAD];
    __shared__ __align__(16) float xj_s[32 * XPAD];
    __shared__ __align__(16) float wt[64 * 64];   // W_att transposed: wt[e][d]
    __shared__ float batt[64], aw[64];
    __shared__ float st[32 * 33];                 // mirror transpose staging

    const int b   = blockIdx.y;
    const int tid = threadIdx.x;

    const int ti  = c_ti[blockIdx.x];
    const int tj  = c_tj[blockIdx.x];
    const int gi0 = ti * 32, gj0 = tj * 32;

    {
        const float4* xa = (const float4*)(x + ((size_t)b * N_ + gi0) * DIN_);
        const float4* xb = (const float4*)(x + ((size_t)b * N_ + gj0) * DIN_);
        #pragma unroll
        for (int t = tid; t < 512; t += 256) {
            int r = t >> 4, c = t & 15;
            ((float4*)(xi_s + r * XPAD))[c] = xa[t];
            ((float4*)(xj_s + r * XPAD))[c] = xb[t];
        }
    }
    #pragma unroll
    for (int t = tid; t < 4096; t += 256) {
        int d = t >> 6, e = t & 63;
        wt[e * 64 + d] = W_att[t];
    }
    if (tid < 64) { batt[tid] = b_att[tid]; aw[tid] = att_w[tid]; }
    __syncthreads();

    const int jl = tid & 31;
    const int w  = tid >> 5;
    const float* xj = xj_s + jl * XPAD;

    #pragma unroll
    for (int qp = 0; qp < 2; qp++) {
        const int il_a = w + 8 * qp;        // rows: {w, w+16} then {w+8, w+24}
        const int il_b = il_a + 16;
        const float* xia = xi_s + il_a * XPAD;
        const float* xib = xi_s + il_b * XPAD;

        // two packed pr sets: 2 x 32 f32x2 = 128 regs
        u64t pra[32], prb[32];
        #pragma unroll
        for (int c = 0; c < 16; c++) {
            ulonglong2 av = ((const ulonglong2*)xia)[c];  // broadcast LDS
            ulonglong2 bv = ((const ulonglong2*)xib)[c];  // broadcast LDS
            ulonglong2 jv = ((const ulonglong2*)xj)[c];   // per-lane
            pra[2*c + 0] = fmul2(av.x, jv.x);
            pra[2*c + 1] = fmul2(av.y, jv.y);
            prb[2*c + 0] = fmul2(bv.x, jv.x);
            prb[2*c + 1] = fmul2(bv.y, jv.y);
        }

        float lga = 0.0f, lgb = 0.0f;
        #pragma unroll 2
        for (int e = 0; e < 64; e++) {
            const ulonglong2* wr = (const ulonglong2*)(wt + e * 64); // broadcast
            u64t a0 = 0ull, a1 = 0ull, b0 = 0ull, b1 = 0ull;
            #pragma unroll
            for (int c = 0; c < 4; c++) {
                ulonglong2 w0 = wr[c];
                a0 = ffma2(pra[2*c + 0],  w0.x, a0);
                a0 = ffma2(pra[2*c + 1],  w0.y, a0);
                b0 = ffma2(prb[2*c + 0],  w0.x, b0);
                b0 = ffma2(prb[2*c + 1],  w0.y, b0);
                ulonglong2 w1 = wr[c + 4];
                a1 = ffma2(pra[2*c + 8],  w1.x, a1);
                a1 = ffma2(pra[2*c + 9],  w1.y, a1);
                b1 = ffma2(prb[2*c + 8],  w1.x, b1);
                b1 = ffma2(prb[2*c + 9],  w1.y, b1);
                ulonglong2 w2 = wr[c + 8];
                a0 = ffma2(pra[2*c + 16], w2.x, a0);
                a0 = ffma2(pra[2*c + 17], w2.y, a0);
                b0 = ffma2(prb[2*c + 16], w2.x, b0);
                b0 = ffma2(prb[2*c + 17], w2.y, b0);
                ulonglong2 w3 = wr[c + 12];
                a1 = ffma2(pra[2*c + 24], w3.x, a1);
                a1 = ffma2(pra[2*c + 25], w3.y, a1);
                b1 = ffma2(prb[2*c + 24], w3.x, b1);
                b1 = ffma2(prb[2*c + 25], w3.y, b1);
            }
            u64t sa = fadd2(a0, a1);
            u64t sb = fadd2(b0, b1);
            float va = __uint_as_float((unsigned)(sa & 0xFFFFFFFFull))
                     + __uint_as_float((unsigned)(sa >> 32)) + batt[e];
            float vb = __uint_as_float((unsigned)(sb & 0xFFFFFFFFull))
                     + __uint_as_float((unsigned)(sb >> 32)) + batt[e];
            float awe = aw[e];
            lga = fmaf(tanh_fast(va), awe, lga);
            lgb = fmaf(tanh_fast(vb), awe, lgb);
        }
        lga *= 0.5f;   // / TEMP
        lgb *= 0.5f;

        g_logits[((size_t)b * N_ + gi0 + il_a) * N_ + gj0 + jl] = lga;
        g_logits[((size_t)b * N_ + gi0 + il_b) * N_ + gj0 + jl] = lgb;
        st[il_a * 33 + jl] = lga;
        st[il_b * 33 + jl] = lgb;
    }

    if (ti != tj) {
        __syncthreads();
        #pragma unroll
        for (int t = tid; t < 1024; t += 256) {
            int r = t >> 5, c = t & 31;
            g_logits[((size_t)b * N_ + gj0 + r) * N_ + gi0 + c] = st[c * 33 + r];
        }
    }
}

// ============================================================================
// Kernel 2: warp-per-row epilogue. Grid (32, B), block 256 = 8 warps.
// No __syncthreads; shfl reductions only.
// ============================================================================
__global__ void __launch_bounds__(256)
epilogue_kernel(const float* __restrict__ x,
                const float* __restrict__ W_pwa, const float* __restrict__ b_pwa,
                const float* __restrict__ W_pna, const float* __restrict__ b_pna,
                const float* __restrict__ bn_scale, const float* __restrict__ bn_bias,
                const float* __restrict__ pool_w, const float* __restrict__ pool_b)
{
    __shared__ float A_sm[8][256];
    __shared__ float agg_sm[8][64];

    const int b    = blockIdx.y;
    const int warp = threadIdx.x >> 5;
    const int lane = threadIdx.x & 31;
    const int i    = blockIdx.x * 8 + warp;

    // softmax over row i (8 logits per lane, stride 32: coalesced)
    const float* lrow = g_logits + ((size_t)b * N_ + i) * N_;
    float lg[8];
    #pragma unroll
    for (int k = 0; k < 8; k++) lg[k] = lrow[lane + 32 * k];
    float mx = lg[0];
    #pragma unroll
    for (int k = 1; k < 8; k++) mx = fmaxf(mx, lg[k]);
    #pragma unroll
    for (int o = 16; o; o >>= 1) mx = fmaxf(mx, __shfl_xor_sync(~0u, mx, o));
    float wv[8], sum = 0.f;
    #pragma unroll
    for (int k = 0; k < 8; k++) { wv[k] = __expf(lg[k] - mx); sum += wv[k]; }
    #pragma unroll
    for (int o = 16; o; o >>= 1) sum += __shfl_xor_sync(~0u, sum, o);
    float inv = 1.0f / sum;
    #pragma unroll
    for (int k = 0; k < 8; k++) A_sm[warp][lane + 32 * k] = wv[k] * inv;
    __syncwarp();

    // agg[d] for d = 2*lane, 2*lane+1
    const float* xb = x + (size_t)b * N_ * DIN_;
    const float* asrc = A_sm[warp];
    float s0 = 0.f, s1 = 0.f;
    #pragma unroll 4
    for (int j = 0; j < N_; j++) {
        float2 xv = *(const float2*)(xb + j * DIN_ + 2 * lane);
        float aj = asrc[j];
        s0 = fmaf(aj, xv.x, s0);
        s1 = fmaf(aj, xv.y, s1);
    }
    agg_sm[warp][2 * lane]     = s0;
    agg_sm[warp][2 * lane + 1] = s1;
    __syncwarp();

    // h for e = 2*lane, 2*lane+1
    const int e0 = 2 * lane;
    float2 bpw = *(const float2*)(b_pwa + e0);
    float2 bpn = *(const float2*)(b_pna + e0);
    float h0 = bpw.x + bpn.x, h1 = bpw.y + bpn.y;
    const float* aggp = agg_sm[warp];
    const float* xi = xb + i * DIN_;
    #pragma unroll 4
    for (int d = 0; d < DIN_; d++) {
        float2 wp = *(const float2*)(W_pwa + d * 64 + e0);
        float2 wn = *(const float2*)(W_pna + d * 64 + e0);
        float ad = aggp[d];
        float xd = xi[d];
        h0 = fmaf(ad, wp.x, h0); h1 = fmaf(ad, wp.y, h1);
        h0 = fmaf(xd, wn.x, h0); h1 = fmaf(xd, wn.y, h1);
    }
    float2 bs = *(const float2*)(bn_scale + e0);
    float2 bz = *(const float2*)(bn_bias + e0);
    const float inv_std = rsqrtf(1.0f + 1e-5f);
    h0 = fmaf(h0, bs.x * inv_std, bz.x);
    h1 = fmaf(h1, bs.y * inv_std, bz.y);
    const float SC = 1.0507009873554805f;
    const float AL = 1.6732632423543772f;
    h0 = (h0 > 0.f) ? SC * h0 : SC * AL * expm1f(h0);
    h1 = (h1 > 0.f) ? SC * h1 : SC * AL * expm1f(h1);
    *(float2*)(g_h + ((size_t)b * N_ + i) * DOUT_ + e0) = make_float2(h0, h1);

    float2 pw = *(const float2*)(pool_w + e0);
    float v = h0 * pw.x + h1 * pw.y;
    #pragma unroll
    for (int o = 16; o; o >>= 1) v += __shfl_xor_sync(~0u, v, o);
    if (lane == 0)
        g_scores[b * N_ + i] = 1.0f / (1.0f + __expf(-(v + pool_b[0])));
}

// ============================================================================
// Kernel 3: sync-free exact top-k by rank counting + coalesced gather
// ============================================================================
__global__ void __launch_bounds__(256)
topk_kernel(float* __restrict__ out)
{
    __shared__ unsigned long long keys[N_];
    __shared__ int   inv[K_];
    __shared__ float ssc[K_];
    const int b = blockIdx.x, tid = threadIdx.x;

    float sc = g_scores[b * N_ + tid];
    unsigned long long mykey =
        ((unsigned long long)__float_as_uint(sc) << 32)
        | (unsigned)(0xFFFFFFFFu - (unsigned)tid);
    keys[tid] = mykey;
    __syncthreads();

    int rank = 0;
    #pragma unroll 8
    for (int j = 0; j < N_; j++) rank += (keys[j] > mykey);   // broadcast LDS
    if (rank < K_) { inv[rank] = tid; ssc[rank] = sc; }
    __syncthreads();

    #pragma unroll
    for (int t = tid; t < K_ * DOUT_; t += N_) {
        int r = t >> 6, e = t & 63;
        out[((size_t)b * K_ + r) * DOUT_ + e] =
            g_h[((size_t)b * N_ + inv[r]) * DOUT_ + e] * ssc[r];
    }
}

extern "C" void kernel_launch(void* const* d_in, const int* in_sizes, int n_in,
                              void* d_out, int out_size)
{
    const float* x        = (const float*)d_in[0];
    const float* W_att    = (const float*)d_in[1];
    const float* b_att    = (const float*)d_in[2];
    const float* att_w    = (const float*)d_in[3];
    const float* W_pwa    = (const float*)d_in[4];
    const float* b_pwa    = (const float*)d_in[5];
    const float* W_pna    = (const float*)d_in[6];
    const float* b_pna    = (const float*)d_in[7];
    const float* bn_scale = (const float*)d_in[8];
    const float* bn_bias  = (const float*)d_in[9];
    const float* pool_w   = (const float*)d_in[10];
    const float* pool_b   = (const float*)d_in[11];
    float* out = (float*)d_out;

    logits_kernel<<<dim3(36, B_), 256>>>(x, W_att, b_att, att_w);
    epilogue_kernel<<<dim3(32, B_), 256>>>(x, W_pwa, b_pwa, W_pna, b_pna,
                                           bn_scale, bn_bias, pool_w, pool_b);
    topk_kernel<<<B_, 256>>>(out);
}